// round 6
// baseline (speedup 1.0000x reference)
#include <cuda_runtime.h>
#include <cuda_bf16.h>
#include <math.h>

#define BB 8
#define NN 8192
#define DD 128
#define DVV 128
#define MM 256
#define NSPLIT 16

#define SCALE_U 0.29730177875068026f   // 128^-0.25
#define H_SCALE 0.04419417382415922f   // 1/(2*sqrt(128))
#define INV_SQRT_M 0.0625f             // 1/sqrt(256)

typedef unsigned long long ull;
typedef unsigned int u32;

// ---------------------------------------------------------------------------
// Device scratch (allocation-free rule). g_U/g_h are reused by the Q pass
// after kv_mma has consumed the K-path values.
// ---------------------------------------------------------------------------
__device__ float g_U[(size_t)BB * NN * MM];      // raw scaled U (K pass, then Q pass)
__device__ float g_h[BB * NN];
__device__ float g_bmax[BB];
__device__ float g_KVpart[NSPLIT][BB * DVV * MM];   // KV^T partials [b][dv][m]
__device__ float g_KsumPart[NSPLIT][BB * MM];
__device__ float g_Ksum[BB * MM];
__device__ float g_rinv[BB * NN];
__device__ __nv_bfloat16 g_omegaT_hi[MM * DD];   // [m][d], pre-scaled by SCALE_U
__device__ __nv_bfloat16 g_omegaT_lo[MM * DD];
__device__ __nv_bfloat16 g_Qp_hi[(size_t)BB * NN * MM];   // [b][n][m]
__device__ __nv_bfloat16 g_Qp_lo[(size_t)BB * NN * MM];
__device__ __nv_bfloat16 g_KVT_hi[BB * DVV * MM];         // [b][dv][m]
__device__ __nv_bfloat16 g_KVT_lo[BB * DVV * MM];

// ---------------------------------------------------------------------------
// PTX helpers (sm_80-level: compile on compute_103)
// ---------------------------------------------------------------------------
__device__ __forceinline__ u32 smem_u32(const void* p) {
    u32 a;
    asm("{ .reg .u64 t; cvta.to.shared.u64 t, %1; cvt.u32.u64 %0, t; }" : "=r"(a) : "l"(p));
    return a;
}
__device__ __forceinline__ void ldsm_x4(u32& r0, u32& r1, u32& r2, u32& r3, u32 addr) {
    asm volatile("ldmatrix.sync.aligned.m8n8.x4.shared.b16 {%0,%1,%2,%3}, [%4];"
                 : "=r"(r0), "=r"(r1), "=r"(r2), "=r"(r3) : "r"(addr));
}
__device__ __forceinline__ void ldsm_x4t(u32& r0, u32& r1, u32& r2, u32& r3, u32 addr) {
    asm volatile("ldmatrix.sync.aligned.m8n8.x4.trans.shared.b16 {%0,%1,%2,%3}, [%4];"
                 : "=r"(r0), "=r"(r1), "=r"(r2), "=r"(r3) : "r"(addr));
}
__device__ __forceinline__ void mma_bf16(float* c, const u32* a, const u32* b) {
    asm volatile("mma.sync.aligned.m16n8k16.row.col.f32.bf16.bf16.f32 "
                 "{%0,%1,%2,%3}, {%4,%5,%6,%7}, {%8,%9}, {%0,%1,%2,%3};"
                 : "+f"(c[0]), "+f"(c[1]), "+f"(c[2]), "+f"(c[3])
                 : "r"(a[0]), "r"(a[1]), "r"(a[2]), "r"(a[3]), "r"(b[0]), "r"(b[1]));
}
__device__ __forceinline__ u32 bpack(float lo, float hi) {
    u32 r;
    asm("cvt.rn.bf16x2.f32 %0, %1, %2;" : "=r"(r) : "f"(hi), "f"(lo));
    return r;
}
__device__ __forceinline__ void cvt8(const float* x, uint4& h4, uint4& l4) {
    u32 h[4], l[4];
    #pragma unroll
    for (int i = 0; i < 4; i++) {
        u32 p = bpack(x[2 * i], x[2 * i + 1]);
        h[i] = p;
        float r0 = x[2 * i]     - __uint_as_float(p << 16);
        float r1 = x[2 * i + 1] - __uint_as_float(p & 0xFFFF0000u);
        l[i] = bpack(r0, r1);
    }
    h4 = make_uint4(h[0], h[1], h[2], h[3]);
    l4 = make_uint4(l[0], l[1], l[2], l[3]);
}

__device__ __forceinline__ float fexp(float x) {
    x = fmaxf(x, -87.0f);
    float t = x * 1.4426950408889634f;
    float r = rintf(t);
    float f = t - r;
    float z = f * 0.6931471805599453f;
    float p = 1.0f + z * (1.0f + z * (0.5f + z * (0.16666667f +
              z * (0.041666667f + z * (0.0083333333f + z * 0.0013888889f)))));
    return __int_as_float(((int)r + 127) << 23) * p;
}
__device__ __forceinline__ float warpMax(float v) {
    #pragma unroll
    for (int o = 16; o; o >>= 1) v = fmaxf(v, __shfl_xor_sync(0xffffffffu, v, o));
    return v;
}
__device__ __forceinline__ void atomicMaxFloat(float* addr, float val) {
    int old = __float_as_int(*addr);
    while (__int_as_float(old) < val) {
        int prev = atomicCAS((int*)addr, old, __float_as_int(val));
        if (prev == old) break;
        old = prev;
    }
}

__global__ void init_kernel() {
    if (threadIdx.x < BB) g_bmax[threadIdx.x] = -INFINITY;
}

__global__ void prep_omega(const float* __restrict__ omega) {
    int d = blockIdx.x;
    for (int m = threadIdx.x; m < MM; m += blockDim.x) {
        float w = omega[d * MM + m] * SCALE_U;
        __nv_bfloat16 h = __float2bfloat16(w);
        g_omegaT_hi[m * DD + d] = h;
        g_omegaT_lo[m * DD + d] = __float2bfloat16(w - __bfloat162float(h));
    }
}

// ---------------------------------------------------------------------------
// proj2: projection, CTA = 64 tok x 128 m, K=128 d. 2 CTAs/SM (96KB smem).
// Warp tile 32 tok x 32 m (8 warps: 2 tok-groups x 4 m-groups).
// kmode=1: track per-batch max (K path). kmode=0: Q path (U/h only).
// smem: sA hi@0 (16K) lo@16K, sB hi@32K (32K) lo@64K. Epilogue sU overlays sB.
// ---------------------------------------------------------------------------
#define P2_SA 0
#define P2_SA_LO 16384
#define P2_SB 32768
#define P2_SB_LO 65536
#define P2_SMEM 98304
#define SU_STRIDE 132

__global__ void __launch_bounds__(256, 2)
proj2_mma(const float* __restrict__ Xin, int kmode) {
    extern __shared__ __align__(16) char dyn[];
    __shared__ float sHred[256];
    __shared__ float wred[8];

    const int tid = threadIdx.x;
    const int lane = tid & 31;
    const int w = tid >> 5;
    const int b = blockIdx.z;
    const int n0 = blockIdx.x * 64;
    const int m0 = blockIdx.y * 128;
    const u32 sbase = smem_u32(dyn);

    float c[2][4][4];
    #pragma unroll
    for (int mb = 0; mb < 2; mb++)
        #pragma unroll
        for (int nb = 0; nb < 4; nb++)
            #pragma unroll
            for (int q = 0; q < 4; q++) c[mb][nb][q] = 0.f;

    const float* Xb = Xin + ((size_t)b * NN + n0) * DD;

    {   // A: 64 tok x 128 d, f32 -> bf16 hi/lo, swizzled; h partials
        int row = tid >> 2, seg = (tid & 3) * 32;
        const float* src = Xb + (size_t)row * DD + seg;
        float hs = 0.f;
        #pragma unroll
        for (int q = 0; q < 4; q++) {
            float x[8];
            float4 v0 = *(const float4*)(src + q * 8);
            float4 v1 = *(const float4*)(src + q * 8 + 4);
            x[0] = v0.x; x[1] = v0.y; x[2] = v0.z; x[3] = v0.w;
            x[4] = v1.x; x[5] = v1.y; x[6] = v1.z; x[7] = v1.w;
            #pragma unroll
            for (int e = 0; e < 8; e++) hs = fmaf(x[e], x[e], hs);
            uint4 h4, l4;
            cvt8(x, h4, l4);
            int chunk = ((seg >> 3) + q) ^ (row & 7);
            *(uint4*)(dyn + P2_SA + row * 256 + (chunk << 4)) = h4;
            *(uint4*)(dyn + P2_SA_LO + row * 256 + (chunk << 4)) = l4;
        }
        sHred[tid] = hs;
    }
    {   // B: omegaT rows m0..m0+127 (2 threads per m-row), swizzled
        int row = tid >> 1, half = tid & 1;
        const uint4* gh = (const uint4*)(g_omegaT_hi + (size_t)(m0 + row) * DD + half * 64);
        const uint4* gl = (const uint4*)(g_omegaT_lo + (size_t)(m0 + row) * DD + half * 64);
        #pragma unroll
        for (int q = 0; q < 8; q++) {
            int sc = ((half * 8 + q) ^ (row & 7)) << 4;
            *(uint4*)(dyn + P2_SB + row * 256 + sc) = gh[q];
            *(uint4*)(dyn + P2_SB_LO + row * 256 + sc) = gl[q];
        }
    }
    __syncthreads();

    const int tg = w & 1;
    const int mg = w >> 1;
    const int rowA0 = tg * 32 + ((lane >> 3) & 1) * 8 + (lane & 7);
    const int kselA = (lane >> 4) & 1;
    const int rowB0 = mg * 32 + ((lane >> 4) & 1) * 8 + (lane & 7);
    const int kselB = (lane >> 3) & 1;

    #pragma unroll
    for (int ks = 0; ks < 8; ks++) {
        int kc = ks * 2;
        u32 ah[2][4], al[2][4];
        #pragma unroll
        for (int mb = 0; mb < 2; mb++) {
            int row = rowA0 + mb * 16;
            u32 adr = sbase + P2_SA + row * 256 + (((kc + kselA) ^ (row & 7)) << 4);
            ldsm_x4(ah[mb][0], ah[mb][1], ah[mb][2], ah[mb][3], adr);
            ldsm_x4(al[mb][0], al[mb][1], al[mb][2], al[mb][3], adr + 16384);
        }
        u32 bh[4][2], bl[4][2];
        #pragma unroll
        for (int nbp = 0; nbp < 2; nbp++) {
            int row = rowB0 + nbp * 16;
            u32 adr = sbase + P2_SB + row * 256 + (((kc + kselB) ^ (row & 7)) << 4);
            u32 r0, r1, r2, r3;
            ldsm_x4(r0, r1, r2, r3, adr);
            bh[2 * nbp][0] = r0; bh[2 * nbp][1] = r1;
            bh[2 * nbp + 1][0] = r2; bh[2 * nbp + 1][1] = r3;
            ldsm_x4(r0, r1, r2, r3, adr + 32768);
            bl[2 * nbp][0] = r0; bl[2 * nbp][1] = r1;
            bl[2 * nbp + 1][0] = r2; bl[2 * nbp + 1][1] = r3;
        }
        #pragma unroll
        for (int mb = 0; mb < 2; mb++)
            #pragma unroll
            for (int nb = 0; nb < 4; nb++) {
                mma_bf16(c[mb][nb], ah[mb], bh[nb]);
                mma_bf16(c[mb][nb], al[mb], bh[nb]);
                mma_bf16(c[mb][nb], ah[mb], bl[nb]);
            }
    }
    __syncthreads();

    // epilogue: c -> sU (overlays sB), track local max
    float* sU = (float*)(dyn + P2_SB);
    float lmax = -INFINITY;
    {
        const int gid = lane >> 2, tig = lane & 3;
        #pragma unroll
        for (int mb = 0; mb < 2; mb++)
            #pragma unroll
            for (int nb = 0; nb < 4; nb++) {
                int r0 = tg * 32 + mb * 16 + gid;
                int m = mg * 32 + nb * 8 + 2 * tig;
                float2 p0 = make_float2(c[mb][nb][0], c[mb][nb][1]);
                float2 p1 = make_float2(c[mb][nb][2], c[mb][nb][3]);
                *(float2*)&sU[r0 * SU_STRIDE + m] = p0;
                *(float2*)&sU[(r0 + 8) * SU_STRIDE + m] = p1;
                lmax = fmaxf(lmax, fmaxf(fmaxf(p0.x, p0.y), fmaxf(p1.x, p1.y)));
            }
    }
    __syncthreads();

    {   // stream U out
        int row = tid >> 2, seg = (tid & 3) * 32;
        float* dst = g_U + ((size_t)(b * NN + n0 + row)) * MM + m0 + seg;
        const float* srcr = sU + row * SU_STRIDE + seg;
        #pragma unroll
        for (int q = 0; q < 8; q++)
            *(float4*)(dst + q * 4) = *(const float4*)(srcr + q * 4);
    }
    if (blockIdx.y == 0 && tid < 64) {
        float h = sHred[tid * 4] + sHred[tid * 4 + 1] + sHred[tid * 4 + 2] + sHred[tid * 4 + 3];
        g_h[b * NN + n0 + tid] = h * H_SCALE;
    }
    if (kmode) {
        lmax = warpMax(lmax);
        if ((tid & 31) == 0) wred[tid >> 5] = lmax;
        __syncthreads();
        if (tid == 0) {
            float m = wred[0];
            #pragma unroll
            for (int q = 1; q < 8; q++) m = fmaxf(m, wred[q]);
            atomicMaxFloat(&g_bmax[b], m);
        }
    }
}

// ---------------------------------------------------------------------------
// qexp: per-token epilogue for the Q path. Reads raw U (g_U) + h, computes
// max/exp/norm, writes Qp hi/lo (bf16) + rinv. 4 threads per token.
// ---------------------------------------------------------------------------
__global__ void __launch_bounds__(256)
qexp_kernel(const float* __restrict__ mask) {
    __shared__ float sKsum[MM];
    const int tid = threadIdx.x;
    const int b = blockIdx.y;
    const int n0 = blockIdx.x * 64;

    if (tid < MM) sKsum[tid] = g_Ksum[b * MM + tid];
    __syncthreads();

    const int tok = tid >> 2, t4 = tid & 3;
    const int seg = t4 * 64;
    const float* Urow = g_U + ((size_t)(b * NN + n0 + tok)) * MM + seg;

    float u[64];
    float mx = -INFINITY;
    #pragma unroll
    for (int q = 0; q < 16; q++) {
        float4 v = *(const float4*)(Urow + q * 4);
        u[q * 4] = v.x; u[q * 4 + 1] = v.y; u[q * 4 + 2] = v.z; u[q * 4 + 3] = v.w;
        mx = fmaxf(mx, fmaxf(fmaxf(v.x, v.y), fmaxf(v.z, v.w)));
    }
    mx = fmaxf(mx, __shfl_xor_sync(0xffffffffu, mx, 1));
    mx = fmaxf(mx, __shfl_xor_sync(0xffffffffu, mx, 2));

    float h = g_h[b * NN + n0 + tok];
    float s = INV_SQRT_M * mask[b * NN + n0 + tok];
    const size_t gbase = ((size_t)(b * NN + n0 + tok)) * MM + seg;

    float np = 0.f;
    #pragma unroll
    for (int q = 0; q < 8; q++) {
        u32 h4[4], l4[4];
        #pragma unroll
        for (int e = 0; e < 4; e++) {
            int i = q * 8 + 2 * e;
            float q0 = (fexp(u[i] - h - mx) + 1e-4f) * s;
            float q1 = (fexp(u[i + 1] - h - mx) + 1e-4f) * s;
            np = fmaf(q0, sKsum[seg + i], np);
            np = fmaf(q1, sKsum[seg + i + 1], np);
            u32 p = bpack(q0, q1);
            h4[e] = p;
            float r0 = q0 - __uint_as_float(p << 16);
            float r1 = q1 - __uint_as_float(p & 0xFFFF0000u);
            l4[e] = bpack(r0, r1);
        }
        *(uint4*)&g_Qp_hi[gbase + q * 8] = make_uint4(h4[0], h4[1], h4[2], h4[3]);
        *(uint4*)&g_Qp_lo[gbase + q * 8] = make_uint4(l4[0], l4[1], l4[2], l4[3]);
    }
    np += __shfl_xor_sync(0xffffffffu, np, 1);
    np += __shfl_xor_sync(0xffffffffu, np, 2);
    if (t4 == 0) g_rinv[b * NN + n0 + tok] = 1.0f / (np + 1e-8f);
}

// ---------------------------------------------------------------------------
// kv_mma: KVT[dv][m] = sum_n V[n][dv]*Kp[n][m]; trans-ldmatrix both operands.
// CTA 128 dv x 64 m per n-split of 512 (8 chunks of 64).
// ---------------------------------------------------------------------------
#define KV_SV 0
#define KV_SV_LO 16384
#define KV_SKP 32768
#define KV_SKP_LO 40960
#define KV_SMEM 49152

__global__ void __launch_bounds__(256, 2)
kv_mma(const float* __restrict__ V, const float* __restrict__ mask) {
    extern __shared__ __align__(16) char dyn[];
    __shared__ float sred[256];

    const int tid = threadIdx.x;
    const int lane = tid & 31;
    const int w = tid >> 5;
    const int b = blockIdx.z;
    const int m0blk = blockIdx.y * 64;
    const int split = blockIdx.x;
    const float mx = g_bmax[b];
    const u32 sbase = smem_u32(dyn);

    const int dv0 = (w & 3) * 32;
    const int m0w = (w >> 2) * 32;
    const int gid = lane >> 2, tig = lane & 3;

    float c[2][4][4];
    #pragma unroll
    for (int mb = 0; mb < 2; mb++)
        #pragma unroll
        for (int nb = 0; nb < 4; nb++)
            #pragma unroll
            for (int q = 0; q < 4; q++) c[mb][nb][q] = 0.f;
    float ksloc[16];
    #pragma unroll
    for (int i = 0; i < 16; i++) ksloc[i] = 0.f;

    const int nbase = split * (NN / NSPLIT);
    for (int ch = 0; ch < (NN / NSPLIT) / 64; ch++) {
        const int n0c = nbase + ch * 64;
        {   // V: [64 n][128 dv] -> bf16 hi/lo swizzled
            int row = tid >> 2, seg = (tid & 3) * 32;
            const float* src = V + ((size_t)(b * NN + n0c + row)) * DVV + seg;
            #pragma unroll
            for (int q = 0; q < 4; q++) {
                float x[8];
                float4 v0 = *(const float4*)(src + q * 8);
                float4 v1 = *(const float4*)(src + q * 8 + 4);
                x[0] = v0.x; x[1] = v0.y; x[2] = v0.z; x[3] = v0.w;
                x[4] = v1.x; x[5] = v1.y; x[6] = v1.z; x[7] = v1.w;
                uint4 h4, l4;
                cvt8(x, h4, l4);
                int chunk = ((seg >> 3) + q) ^ (row & 7);
                *(uint4*)(dyn + KV_SV + row * 256 + (chunk << 4)) = h4;
                *(uint4*)(dyn + KV_SV_LO + row * 256 + (chunk << 4)) = l4;
            }
        }
        {   // Kp: exp(U - h - mx), [64 n][64 m] bf16 hi/lo swizzled
            int n = tid >> 2, mseg = (tid & 3) * 16;
            const float* up = g_U + ((size_t)(b * NN + n0c + n)) * MM + m0blk + mseg;
            float hh = g_h[b * NN + n0c + n];
            float s = INV_SQRT_M * mask[b * NN + n0c + n];
            float off = hh + mx;
            float kp[16];
            #pragma unroll
            for (int q = 0; q < 4; q++) {
                float4 u4 = *(const float4*)(up + q * 4);
                kp[q * 4 + 0] = (fexp(u4.x - off) + 1e-4f) * s;
                kp[q * 4 + 1] = (fexp(u4.y - off) + 1e-4f) * s;
                kp[q * 4 + 2] = (fexp(u4.z - off) + 1e-4f) * s;
                kp[q * 4 + 3] = (fexp(u4.w - off) + 1e-4f) * s;
            }
            #pragma unroll
            for (int i = 0; i < 16; i++) ksloc[i] += kp[i];
            #pragma unroll
            for (int q = 0; q < 2; q++) {
                uint4 h4, l4;
                cvt8(kp + q * 8, h4, l4);
                int chunk = (2 * (tid & 3) + q) ^ (n & 7);
                *(uint4*)(dyn + KV_SKP + n * 128 + (chunk << 4)) = h4;
                *(uint4*)(dyn + KV_SKP_LO + n * 128 + (chunk << 4)) = l4;
            }
        }
        __syncthreads();

        #pragma unroll
        for (int ks = 0; ks < 4; ks++) {
            const int kk = ks * 16;
            u32 avh[2][4], avl[2][4];
            {
                int row = kk + ((lane >> 4) & 1) * 8 + (lane & 7);
                int cb = (dv0 >> 3) + ((lane >> 3) & 1);
                #pragma unroll
                for (int mb = 0; mb < 2; mb++) {
                    int chunk = (cb + mb * 2) ^ (row & 7);
                    u32 adr = sbase + KV_SV + row * 256 + (chunk << 4);
                    ldsm_x4t(avh[mb][0], avh[mb][1], avh[mb][2], avh[mb][3], adr);
                    ldsm_x4t(avl[mb][0], avl[mb][1], avl[mb][2], avl[mb][3], adr + 16384);
                }
            }
            u32 bh[4][2], bl[4][2];
            {
                int row = kk + ((lane >> 3) & 1) * 8 + (lane & 7);
                int cb = (m0w >> 3) + ((lane >> 4) & 1);
                #pragma unroll
                for (int nbp = 0; nbp < 2; nbp++) {
                    int chunk = (cb + nbp * 2) ^ (row & 7);
                    u32 adr = sbase + KV_SKP + row * 128 + (chunk << 4);
                    u32 r0, r1, r2, r3;
                    ldsm_x4t(r0, r1, r2, r3, adr);
                    bh[2 * nbp][0] = r0; bh[2 * nbp][1] = r1;
                    bh[2 * nbp + 1][0] = r2; bh[2 * nbp + 1][1] = r3;
                    ldsm_x4t(r0, r1, r2, r3, adr + 8192);
                    bl[2 * nbp][0] = r0; bl[2 * nbp][1] = r1;
                    bl[2 * nbp + 1][0] = r2; bl[2 * nbp + 1][1] = r3;
                }
            }
            #pragma unroll
            for (int mb = 0; mb < 2; mb++)
                #pragma unroll
                for (int nb = 0; nb < 4; nb++) {
                    mma_bf16(c[mb][nb], avh[mb], bh[nb]);
                    mma_bf16(c[mb][nb], avl[mb], bh[nb]);
                    mma_bf16(c[mb][nb], avh[mb], bl[nb]);
                }
        }
        __syncthreads();
    }

    float* outp = g_KVpart[split];
    #pragma unroll
    for (int mb = 0; mb < 2; mb++)
        #pragma unroll
        for (int nb = 0; nb < 4; nb++) {
            int dv = dv0 + mb * 16 + gid;
            int m = m0blk + m0w + nb * 8 + 2 * tig;
            *(float2*)&outp[(size_t)(b * DVV + dv) * MM + m] =
                make_float2(c[mb][nb][0], c[mb][nb][1]);
            *(float2*)&outp[(size_t)(b * DVV + dv + 8) * MM + m] =
                make_float2(c[mb][nb][2], c[mb][nb][3]);
        }

    float* sKs = (float*)dyn;   // 64 x 64 f32 (reuses sV region)
    __syncthreads();
    {
        int n = tid >> 2, mseg = (tid & 3) * 16;
        #pragma unroll
        for (int i = 0; i < 16; i++) sKs[n * 64 + mseg + i] = ksloc[i];
    }
    __syncthreads();
    {
        int j = tid & 63, g = tid >> 6;
        float p = 0.f;
        #pragma unroll
        for (int r = 0; r < 16; r++) p += sKs[(g * 16 + r) * 64 + j];
        sred[g * 64 + j] = p;
    }
    __syncthreads();
    if (tid < 64)
        g_KsumPart[split][b * MM + m0blk + tid] =
            sred[tid] + sred[64 + tid] + sred[128 + tid] + sred[192 + tid];
}

__global__ void reduce_kernel() {
    int i = blockIdx.x * 256 + threadIdx.x;
    if (i < BB * DVV * MM) {
        float s = 0.f;
        #pragma unroll
        for (int p = 0; p < NSPLIT; p++) s += g_KVpart[p][i];
        __nv_bfloat16 h = __float2bfloat16(s);
        g_KVT_hi[i] = h;
        g_KVT_lo[i] = __float2bfloat16(s - __bfloat162float(h));
    }
    int j = i - BB * DVV * MM;
    if (j >= 0 && j < BB * MM) {
        float s = 0.f;
        #pragma unroll
        for (int p = 0; p < NSPLIT; p++) s += g_KsumPart[p][j];
        g_Ksum[j] = s;
    }
}

// ---------------------------------------------------------------------------
// out_mma: Out[tok][dv] = (sum_m Qp[tok][m]*KVT[dv][m]) * rinv[tok]
// CTA 128 tok x 128 dv, K=256 in 4 chunks of 64. Warp 32 tok x 64 dv.
// ---------------------------------------------------------------------------
#define O_SA 0
#define O_SA_LO 16384
#define O_SB 32768
#define O_SB_LO 49152
#define O_SMEM 65536

__global__ void __launch_bounds__(256, 2)
out_mma(float* __restrict__ out) {
    extern __shared__ __align__(16) char dyn[];
    const int tid = threadIdx.x;
    const int lane = tid & 31;
    const int w = tid >> 5;
    const int b = blockIdx.y;
    const int n0 = blockIdx.x * 128;
    const u32 sbase = smem_u32(dyn);

    const int tok0 = (w & 3) * 32;
    const int dv0 = (w >> 2) * 64;
    const int gid = lane >> 2, tig = lane & 3;

    float c[2][8][4];
    #pragma unroll
    for (int mb = 0; mb < 2; mb++)
        #pragma unroll
        for (int nb = 0; nb < 8; nb++)
            #pragma unroll
            for (int q = 0; q < 4; q++) c[mb][nb][q] = 0.f;

    const int rowA0 = tok0 + ((lane >> 3) & 1) * 8 + (lane & 7);
    const int kselA = (lane >> 4) & 1;
    const int rowB0 = dv0 + ((lane >> 4) & 1) * 8 + (lane & 7);
    const int kselB = (lane >> 3) & 1;

    for (int kc = 0; kc < 4; kc++) {
        const int mbase = kc * 64;
        {
            int row = tid >> 1, hf = tid & 1;
            const uint4* ah = (const uint4*)(g_Qp_hi + ((size_t)(b * NN + n0 + row)) * MM + mbase + hf * 32);
            const uint4* al = (const uint4*)(g_Qp_lo + ((size_t)(b * NN + n0 + row)) * MM + mbase + hf * 32);
            const uint4* kh = (const uint4*)(g_KVT_hi + (size_t)(b * DVV + row) * MM + mbase + hf * 32);
            const uint4* kl = (const uint4*)(g_KVT_lo + (size_t)(b * DVV + row) * MM + mbase + hf * 32);
            #pragma unroll
            for (int q = 0; q < 4; q++) {
                int chunk = (hf * 4 + q) ^ (row & 7);
                *(uint4*)(dyn + O_SA + row * 128 + (chunk << 4)) = ah[q];
                *(uint4*)(dyn + O_SA_LO + row * 128 + (chunk << 4)) = al[q];
                *(uint4*)(dyn + O_SB + row * 128 + (chunk << 4)) = kh[q];
                *(uint4*)(dyn + O_SB_LO + row * 128 + (chunk << 4)) = kl[q];
            }
        }
        __syncthreads();
        #pragma unroll
        for (int ks = 0; ks < 4; ks++) {
            int kcc = ks * 2;
            u32 ah[2][4], al[2][4];
            #pragma unroll
            for (int mb = 0; mb < 2; mb++) {
                int row = rowA0 + mb * 16;
                u32 adr = sbase + O_SA + row * 128 + (((kcc + kselA) ^ (row & 7)) << 4);
                ldsm_x4(ah[mb][0], ah[mb][1], ah[mb][2], ah[mb][3], adr);
                ldsm_x4(al[mb][0], al[mb][1], al[mb][2], al[mb][3], adr + 16384);
            }
            u32 bh[8][2], bl[8][2];
            #pragma unroll
            for (int nbp = 0; nbp < 4; nbp++) {
                int row = rowB0 + nbp * 16;
                u32 adr = sbase + O_SB + row * 128 + (((kcc + kselB) ^ (row & 7)) << 4);
                u32 r0, r1, r2, r3;
                ldsm_x4(r0, r1, r2, r3, adr);
                bh[2 * nbp][0] = r0; bh[2 * nbp][1] = r1;
                bh[2 * nbp + 1][0] = r2; bh[2 * nbp + 1][1] = r3;
                ldsm_x4(r0, r1, r2, r3, adr + 16384);
                bl[2 * nbp][0] = r0; bl[2 * nbp][1] = r1;
                bl[2 * nbp + 1][0] = r2; bl[2 * nbp + 1][1] = r3;
            }
            #pragma unroll
            for (int mb = 0; mb < 2; mb++)
                #pragma unroll
                for (int nb = 0; nb < 8; nb++) {
                    mma_bf16(c[mb][nb], ah[mb], bh[nb]);
                    mma_bf16(c[mb][nb], al[mb], bh[nb]);
                    mma_bf16(c[mb][nb], ah[mb], bl[nb]);
                }
        }
        __syncthreads();
    }

    #pragma unroll
    for (int mb = 0; mb < 2; mb++) {
        int t0 = tok0 + mb * 16 + gid;
        float r0 = g_rinv[b * NN + n0 + t0];
        float r1 = g_rinv[b * NN + n0 + t0 + 8];
        float* d0 = out + ((size_t)(b * NN + n0 + t0)) * DVV;
        float* d1 = d0 + (size_t)8 * DVV;
        #pragma unroll
        for (int nb = 0; nb < 8; nb++) {
            int dv = dv0 + nb * 8 + 2 * tig;
            *(float2*)(d0 + dv) = make_float2(c[mb][nb][0] * r0, c[mb][nb][1] * r0);
            *(float2*)(d1 + dv) = make_float2(c[mb][nb][2] * r1, c[mb][nb][3] * r1);
        }
    }
}

// ---------------------------------------------------------------------------
extern "C" void kernel_launch(void* const* d_in, const int* in_sizes, int n_in,
                              void* d_out, int out_size) {
    const float* Q     = (const float*)d_in[0];
    const float* K     = (const float*)d_in[1];
    const float* V     = (const float*)d_in[2];
    const float* amask = (const float*)d_in[3];
    const float* omega = (const float*)d_in[4];
    float* out = (float*)d_out;

    cudaFuncSetAttribute(proj2_mma, cudaFuncAttributeMaxDynamicSharedMemorySize, P2_SMEM);
    cudaFuncSetAttribute(kv_mma,    cudaFuncAttributeMaxDynamicSharedMemorySize, KV_SMEM);
    cudaFuncSetAttribute(out_mma,   cudaFuncAttributeMaxDynamicSharedMemorySize, O_SMEM);

    init_kernel<<<1, 32>>>();
    prep_omega<<<DD, 256>>>(omega);
    proj2_mma<<<dim3(NN / 64, MM / 128, BB), 256, P2_SMEM>>>(K, 1);
    kv_mma<<<dim3(NSPLIT, MM / 64, BB), 256, KV_SMEM>>>(V, amask);
    reduce_kernel<<<(BB * DVV * MM + BB * MM + 255) / 256, 256>>>();
    proj2_mma<<<dim3(NN / 64, MM / 128, BB), 256, P2_SMEM>>>(Q, 0);
    qexp_kernel<<<dim3(NN / 64, BB), 256>>>(amask);
    out_mma<<<dim3(NN / 128, BB), 256, O_SMEM>>>(out);
}

// round 7
// speedup vs baseline: 1.3329x; 1.3329x over previous
#include <cuda_runtime.h>
#include <cuda_bf16.h>
#include <math.h>

#define BB 8
#define NN 8192
#define DD 128
#define DVV 128
#define MM 256
#define NSPLIT 16

#define SCALE_U 0.29730177875068026f   // 128^-0.25
#define H_SCALE 0.04419417382415922f   // 1/(2*sqrt(128))
#define INV_SQRT_M 0.0625f             // 1/sqrt(256)

typedef unsigned long long ull;
typedef unsigned int u32;

// ---------------------------------------------------------------------------
// Device scratch
// ---------------------------------------------------------------------------
__device__ float g_U[(size_t)BB * NN * MM];      // raw scaled U (K pass, then Q pass)
__device__ float g_h[BB * NN];
__device__ float g_bmax[BB];
__device__ float g_KVpart[NSPLIT][BB * DVV * MM];   // KV^T partials [b][dv][m]
__device__ float g_KsumPart[NSPLIT][BB * MM];
__device__ float g_Ksum[BB * MM];
__device__ float g_rinv[BB * NN];
// omega pre-packed as mma B-fragments: [kstep(8)][nb(32)][reg(2)][lane(32)] u32
__device__ u32 g_wfrag_hi[8 * 32 * 2 * 32];
__device__ u32 g_wfrag_lo[8 * 32 * 2 * 32];
__device__ __nv_bfloat16 g_Qp_hi[(size_t)BB * NN * MM];   // [b][n][m]
__device__ __nv_bfloat16 g_Qp_lo[(size_t)BB * NN * MM];
__device__ __nv_bfloat16 g_KVT_hi[BB * DVV * MM];         // [b][dv][m]
__device__ __nv_bfloat16 g_KVT_lo[BB * DVV * MM];

// ---------------------------------------------------------------------------
// PTX helpers (sm_80-level)
// ---------------------------------------------------------------------------
__device__ __forceinline__ u32 smem_u32(const void* p) {
    u32 a;
    asm("{ .reg .u64 t; cvta.to.shared.u64 t, %1; cvt.u32.u64 %0, t; }" : "=r"(a) : "l"(p));
    return a;
}
__device__ __forceinline__ void ldsm_x4(u32& r0, u32& r1, u32& r2, u32& r3, u32 addr) {
    asm volatile("ldmatrix.sync.aligned.m8n8.x4.shared.b16 {%0,%1,%2,%3}, [%4];"
                 : "=r"(r0), "=r"(r1), "=r"(r2), "=r"(r3) : "r"(addr));
}
__device__ __forceinline__ void ldsm_x4t(u32& r0, u32& r1, u32& r2, u32& r3, u32 addr) {
    asm volatile("ldmatrix.sync.aligned.m8n8.x4.trans.shared.b16 {%0,%1,%2,%3}, [%4];"
                 : "=r"(r0), "=r"(r1), "=r"(r2), "=r"(r3) : "r"(addr));
}
__device__ __forceinline__ void mma_bf16(float* c, const u32* a, const u32* b) {
    asm volatile("mma.sync.aligned.m16n8k16.row.col.f32.bf16.bf16.f32 "
                 "{%0,%1,%2,%3}, {%4,%5,%6,%7}, {%8,%9}, {%0,%1,%2,%3};"
                 : "+f"(c[0]), "+f"(c[1]), "+f"(c[2]), "+f"(c[3])
                 : "r"(a[0]), "r"(a[1]), "r"(a[2]), "r"(a[3]), "r"(b[0]), "r"(b[1]));
}
__device__ __forceinline__ u32 bpack(float lo, float hi) {
    u32 r;
    asm("cvt.rn.bf16x2.f32 %0, %1, %2;" : "=r"(r) : "f"(hi), "f"(lo));
    return r;
}
__device__ __forceinline__ void cvt8(const float* x, uint4& h4, uint4& l4) {
    u32 h[4], l[4];
    #pragma unroll
    for (int i = 0; i < 4; i++) {
        u32 p = bpack(x[2 * i], x[2 * i + 1]);
        h[i] = p;
        float r0 = x[2 * i]     - __uint_as_float(p << 16);
        float r1 = x[2 * i + 1] - __uint_as_float(p & 0xFFFF0000u);
        l[i] = bpack(r0, r1);
    }
    h4 = make_uint4(h[0], h[1], h[2], h[3]);
    l4 = make_uint4(l[0], l[1], l[2], l[3]);
}

__device__ __forceinline__ float fexp(float x) {
    x = fmaxf(x, -87.0f);
    float t = x * 1.4426950408889634f;
    float r = rintf(t);
    float f = t - r;
    float z = f * 0.6931471805599453f;
    float p = 1.0f + z * (1.0f + z * (0.5f + z * (0.16666667f +
              z * (0.041666667f + z * (0.0083333333f + z * 0.0013888889f)))));
    return __int_as_float(((int)r + 127) << 23) * p;
}
__device__ __forceinline__ float warpMax(float v) {
    #pragma unroll
    for (int o = 16; o; o >>= 1) v = fmaxf(v, __shfl_xor_sync(0xffffffffu, v, o));
    return v;
}
__device__ __forceinline__ void atomicMaxFloat(float* addr, float val) {
    int old = __float_as_int(*addr);
    while (__int_as_float(old) < val) {
        int prev = atomicCAS((int*)addr, old, __float_as_int(val));
        if (prev == old) break;
        old = prev;
    }
}

__global__ void init_kernel() {
    if (threadIdx.x < BB) g_bmax[threadIdx.x] = -INFINITY;
}

// ---------------------------------------------------------------------------
// prep_omega: write omega (scaled, transposed) directly as B-fragments.
// Element omegaT[m][d]: kstep=d>>4, nb=m>>3, reg=(d>>3)&1,
// lane=(m&7)*4+((d&7)>>1), u32 low half = even d.
// ---------------------------------------------------------------------------
__global__ void prep_omega(const float* __restrict__ omega) {
    int id = blockIdx.x * 256 + threadIdx.x;   // 16384 total
    int m = id >> 6;
    int dp = id & 63;
    int d = dp * 2;
    float w0 = omega[(size_t)d * MM + m] * SCALE_U;
    float w1 = omega[(size_t)(d + 1) * MM + m] * SCALE_U;
    u32 hp = bpack(w0, w1);
    float r0 = w0 - __uint_as_float(hp << 16);
    float r1 = w1 - __uint_as_float(hp & 0xFFFF0000u);
    u32 lp = bpack(r0, r1);
    int idx = (((d >> 4) * 32 + (m >> 3)) * 2 + ((d >> 3) & 1)) * 32
            + (m & 7) * 4 + ((d & 7) >> 1);
    g_wfrag_hi[idx] = hp;
    g_wfrag_lo[idx] = lp;
}

// ---------------------------------------------------------------------------
// Projections: CTA = 64 tok x 256 m, K=128. Warp tile 32 tok x 64 m.
// A (X) converted to smem hi/lo + ldsm. B (omega) loaded as frags via LDG.
// smem: sA hi@0 (16K) lo@16K; epilogue sU f32 [64][264] overlays from 0.
// ---------------------------------------------------------------------------
#define P_SA 0
#define P_SA_LO 16384
#define P_SMEM 67584
#define SU_STRIDE 264

__device__ __forceinline__ void proj_mma_main(
    const float* __restrict__ Xb, char* dyn, u32 sb,
    float c[2][8][4], float* sHred)
{
    const int tid = threadIdx.x;
    const int lane = tid & 31;
    const int w = tid >> 5;

    {   // A: 64 tok x 128 d, f32 -> bf16 hi/lo, swizzled; h partials
        int row = tid >> 2, seg = (tid & 3) * 32;
        const float* src = Xb + (size_t)row * DD + seg;
        float hs = 0.f;
        #pragma unroll
        for (int q = 0; q < 4; q++) {
            float x[8];
            float4 v0 = *(const float4*)(src + q * 8);
            float4 v1 = *(const float4*)(src + q * 8 + 4);
            x[0] = v0.x; x[1] = v0.y; x[2] = v0.z; x[3] = v0.w;
            x[4] = v1.x; x[5] = v1.y; x[6] = v1.z; x[7] = v1.w;
            #pragma unroll
            for (int e = 0; e < 8; e++) hs = fmaf(x[e], x[e], hs);
            uint4 h4, l4;
            cvt8(x, h4, l4);
            int chunk = ((seg >> 3) + q) ^ (row & 7);
            *(uint4*)(dyn + P_SA + row * 256 + (chunk << 4)) = h4;
            *(uint4*)(dyn + P_SA_LO + row * 256 + (chunk << 4)) = l4;
        }
        sHred[tid] = hs;
    }
    __syncthreads();

    const int tok0 = (w & 1) * 32;
    const int m0w = (w >> 1) * 64;
    const int rowA0 = tok0 + ((lane >> 3) & 1) * 8 + (lane & 7);
    const int kselA = (lane >> 4) & 1;
    const int nbBase = (m0w >> 3);

    #pragma unroll
    for (int ks = 0; ks < 8; ks++) {
        int kc = ks * 2;
        u32 ah[2][4], al[2][4];
        #pragma unroll
        for (int mb = 0; mb < 2; mb++) {
            int row = rowA0 + mb * 16;
            u32 adr = sb + P_SA + row * 256 + (((kc + kselA) ^ (row & 7)) << 4);
            ldsm_x4(ah[mb][0], ah[mb][1], ah[mb][2], ah[mb][3], adr);
            ldsm_x4(al[mb][0], al[mb][1], al[mb][2], al[mb][3], adr + 16384);
        }
        u32 bh[8][2], bl[8][2];
        #pragma unroll
        for (int nb = 0; nb < 8; nb++) {
            int base = ((ks * 32 + nbBase + nb) * 2) * 32 + lane;
            bh[nb][0] = g_wfrag_hi[base];
            bh[nb][1] = g_wfrag_hi[base + 32];
            bl[nb][0] = g_wfrag_lo[base];
            bl[nb][1] = g_wfrag_lo[base + 32];
        }
        #pragma unroll
        for (int mb = 0; mb < 2; mb++)
            #pragma unroll
            for (int nb = 0; nb < 8; nb++) {
                mma_bf16(c[mb][nb], ah[mb], bh[nb]);
                mma_bf16(c[mb][nb], al[mb], bh[nb]);
                mma_bf16(c[mb][nb], ah[mb], bl[nb]);
            }
    }
    __syncthreads();   // A reads done before sU overlays
}

__device__ __forceinline__ float store_sU(float c[2][8][4], float* sU, int tid) {
    const int lane = tid & 31, w = tid >> 5;
    const int tok0 = (w & 1) * 32, m0w = (w >> 1) * 64;
    const int gid = lane >> 2, tig = lane & 3;
    float lmax = -INFINITY;
    #pragma unroll
    for (int mb = 0; mb < 2; mb++)
        #pragma unroll
        for (int nb = 0; nb < 8; nb++) {
            int r0 = tok0 + mb * 16 + gid;
            int m = m0w + nb * 8 + 2 * tig;
            float2 p0 = make_float2(c[mb][nb][0], c[mb][nb][1]);
            float2 p1 = make_float2(c[mb][nb][2], c[mb][nb][3]);
            *(float2*)&sU[r0 * SU_STRIDE + m] = p0;
            *(float2*)&sU[(r0 + 8) * SU_STRIDE + m] = p1;
            lmax = fmaxf(lmax, fmaxf(fmaxf(p0.x, p0.y), fmaxf(p1.x, p1.y)));
        }
    return lmax;
}

__global__ void __launch_bounds__(256)
kproj_mma(const float* __restrict__ Kin) {
    extern __shared__ __align__(16) char dyn[];
    __shared__ float sHred[256];
    __shared__ float wred[8];

    const int tid = threadIdx.x;
    const int b = blockIdx.y;
    const int n0 = blockIdx.x * 64;
    const u32 sbase = smem_u32(dyn);

    float c[2][8][4];
    #pragma unroll
    for (int mb = 0; mb < 2; mb++)
        #pragma unroll
        for (int nb = 0; nb < 8; nb++)
            #pragma unroll
            for (int q = 0; q < 4; q++) c[mb][nb][q] = 0.f;

    proj_mma_main(Kin + ((size_t)b * NN + n0) * DD, dyn, sbase, c, sHred);

    float* sU = (float*)dyn;
    float lmax = store_sU(c, sU, tid);
    __syncthreads();

    {
        int row = tid >> 2, seg = (tid & 3) * 64;
        float* dst = g_U + ((size_t)(b * NN + n0 + row)) * MM + seg;
        const float* srcr = sU + row * SU_STRIDE + seg;
        #pragma unroll
        for (int q = 0; q < 16; q++)
            *(float4*)(dst + q * 4) = *(const float4*)(srcr + q * 4);
    }
    if (tid < 64) {
        float h = sHred[tid * 4] + sHred[tid * 4 + 1] + sHred[tid * 4 + 2] + sHred[tid * 4 + 3];
        g_h[b * NN + n0 + tid] = h * H_SCALE;
    }
    lmax = warpMax(lmax);
    if ((tid & 31) == 0) wred[tid >> 5] = lmax;
    __syncthreads();
    if (tid == 0) {
        float m = wred[0];
        #pragma unroll
        for (int q = 1; q < 8; q++) m = fmaxf(m, wred[q]);
        atomicMaxFloat(&g_bmax[b], m);
    }
}

__global__ void __launch_bounds__(256)
qproj_mma(const float* __restrict__ Qin, const float* __restrict__ mask) {
    extern __shared__ __align__(16) char dyn[];
    __shared__ float sHred[256];
    __shared__ float sKsum[MM];

    const int tid = threadIdx.x;
    const int b = blockIdx.y;
    const int n0 = blockIdx.x * 64;
    const u32 sbase = smem_u32(dyn);

    if (tid < MM) sKsum[tid] = g_Ksum[b * MM + tid];

    float c[2][8][4];
    #pragma unroll
    for (int mb = 0; mb < 2; mb++)
        #pragma unroll
        for (int nb = 0; nb < 8; nb++)
            #pragma unroll
            for (int q = 0; q < 4; q++) c[mb][nb][q] = 0.f;

    proj_mma_main(Qin + ((size_t)b * NN + n0) * DD, dyn, sbase, c, sHred);

    float* sU = (float*)dyn;
    (void)store_sU(c, sU, tid);
    __syncthreads();

    const int tok = tid >> 2, t4 = tid & 3;
    const int seg = t4 * 64;
    const float* Urow = sU + tok * SU_STRIDE + seg;

    float mx = -INFINITY;
    #pragma unroll
    for (int i = 0; i < 64; i++) mx = fmaxf(mx, Urow[i]);
    mx = fmaxf(mx, __shfl_xor_sync(0xffffffffu, mx, 1));
    mx = fmaxf(mx, __shfl_xor_sync(0xffffffffu, mx, 2));

    float h = (sHred[tok * 4] + sHred[tok * 4 + 1] + sHred[tok * 4 + 2] + sHred[tok * 4 + 3]) * H_SCALE;
    float s = INV_SQRT_M * mask[b * NN + n0 + tok];
    const size_t gbase = ((size_t)(b * NN + n0 + tok)) * MM + seg;

    float np = 0.f;
    #pragma unroll
    for (int q = 0; q < 8; q++) {
        u32 h4[4], l4[4];
        #pragma unroll
        for (int e = 0; e < 4; e++) {
            int i = q * 8 + 2 * e;
            float q0 = (fexp(Urow[i] - h - mx) + 1e-4f) * s;
            float q1 = (fexp(Urow[i + 1] - h - mx) + 1e-4f) * s;
            np = fmaf(q0, sKsum[seg + i], np);
            np = fmaf(q1, sKsum[seg + i + 1], np);
            u32 p = bpack(q0, q1);
            h4[e] = p;
            float r0 = q0 - __uint_as_float(p << 16);
            float r1 = q1 - __uint_as_float(p & 0xFFFF0000u);
            l4[e] = bpack(r0, r1);
        }
        *(uint4*)&g_Qp_hi[gbase + q * 8] = make_uint4(h4[0], h4[1], h4[2], h4[3]);
        *(uint4*)&g_Qp_lo[gbase + q * 8] = make_uint4(l4[0], l4[1], l4[2], l4[3]);
    }
    np += __shfl_xor_sync(0xffffffffu, np, 1);
    np += __shfl_xor_sync(0xffffffffu, np, 2);
    if (t4 == 0) g_rinv[b * NN + n0 + tok] = 1.0f / (np + 1e-8f);
}

// ---------------------------------------------------------------------------
// kv_mma: KVT[dv][m] = sum_n V[n][dv]*Kp[n][m]. CTA 128 dv x 128 m,
// warp tile 32 dv x 64 m (4 dv-groups x 2 m-groups). n-split of 512.
// smem: sV hi@0/lo@16K (64x256B), sKp hi@32K/lo@48K (64x256B) = 64KB.
// ---------------------------------------------------------------------------
#define KV_SV 0
#define KV_SV_LO 16384
#define KV_SKP 32768
#define KV_SKP_LO 49152
#define KV_SMEM 65536

__global__ void __launch_bounds__(256)
kv_mma(const float* __restrict__ V, const float* __restrict__ mask) {
    extern __shared__ __align__(16) char dyn[];

    const int tid = threadIdx.x;
    const int lane = tid & 31;
    const int w = tid >> 5;
    const int b = blockIdx.z;
    const int m0blk = blockIdx.y * 128;
    const int split = blockIdx.x;
    const float mx = g_bmax[b];
    const u32 sbase = smem_u32(dyn);

    const int dv0 = (w & 3) * 32;
    const int m0w = (w >> 2) * 64;
    const int gid = lane >> 2, tig = lane & 3;

    float c[2][8][4];
    #pragma unroll
    for (int mb = 0; mb < 2; mb++)
        #pragma unroll
        for (int nb = 0; nb < 8; nb++)
            #pragma unroll
            for (int q = 0; q < 4; q++) c[mb][nb][q] = 0.f;
    float ksloc[8];
    #pragma unroll
    for (int i = 0; i < 8; i++) ksloc[i] = 0.f;

    const int mg2 = tid & 15;          // Kp conv: m-group (8 m)
    const int ng = tid >> 4;           // Kp conv: n-group (4 n)

    const int nbase = split * (NN / NSPLIT);
    for (int ch = 0; ch < (NN / NSPLIT) / 64; ch++) {
        const int n0c = nbase + ch * 64;
        {   // V: [64 n][128 dv] -> bf16 hi/lo swizzled
            int row = tid >> 2, seg = (tid & 3) * 32;
            const float* src = V + ((size_t)(b * NN + n0c + row)) * DVV + seg;
            #pragma unroll
            for (int q = 0; q < 4; q++) {
                float x[8];
                float4 v0 = *(const float4*)(src + q * 8);
                float4 v1 = *(const float4*)(src + q * 8 + 4);
                x[0] = v0.x; x[1] = v0.y; x[2] = v0.z; x[3] = v0.w;
                x[4] = v1.x; x[5] = v1.y; x[6] = v1.z; x[7] = v1.w;
                uint4 h4, l4;
                cvt8(x, h4, l4);
                int chunk = ((seg >> 3) + q) ^ (row & 7);
                *(uint4*)(dyn + KV_SV + row * 256 + (chunk << 4)) = h4;
                *(uint4*)(dyn + KV_SV_LO + row * 256 + (chunk << 4)) = l4;
            }
        }
        {   // Kp: exp(U - h - mx), [64 n][128 m] bf16 hi/lo swizzled
            #pragma unroll
            for (int r = 0; r < 4; r++) {
                int n = ng * 4 + r;
                const float* up = g_U + ((size_t)(b * NN + n0c + n)) * MM + m0blk + mg2 * 8;
                float off = g_h[b * NN + n0c + n] + mx;
                float s = INV_SQRT_M * mask[b * NN + n0c + n];
                float kp[8];
                float4 u0 = *(const float4*)(up);
                float4 u1 = *(const float4*)(up + 4);
                kp[0] = (fexp(u0.x - off) + 1e-4f) * s;
                kp[1] = (fexp(u0.y - off) + 1e-4f) * s;
                kp[2] = (fexp(u0.z - off) + 1e-4f) * s;
                kp[3] = (fexp(u0.w - off) + 1e-4f) * s;
                kp[4] = (fexp(u1.x - off) + 1e-4f) * s;
                kp[5] = (fexp(u1.y - off) + 1e-4f) * s;
                kp[6] = (fexp(u1.z - off) + 1e-4f) * s;
                kp[7] = (fexp(u1.w - off) + 1e-4f) * s;
                #pragma unroll
                for (int i = 0; i < 8; i++) ksloc[i] += kp[i];
                uint4 h4, l4;
                cvt8(kp, h4, l4);
                int chunk = mg2 ^ (n & 7);
                *(uint4*)(dyn + KV_SKP + n * 256 + (chunk << 4)) = h4;
                *(uint4*)(dyn + KV_SKP_LO + n * 256 + (chunk << 4)) = l4;
            }
        }
        __syncthreads();

        #pragma unroll
        for (int ks = 0; ks < 4; ks++) {
            const int kk = ks * 16;
            u32 avh[2][4], avl[2][4];
            {
                int row = kk + ((lane >> 4) & 1) * 8 + (lane & 7);
                int cb = (dv0 >> 3) + ((lane >> 3) & 1);
                #pragma unroll
                for (int mb = 0; mb < 2; mb++) {
                    int chunk = (cb + mb * 2) ^ (row & 7);
                    u32 adr = sbase + KV_SV + row * 256 + (chunk << 4);
                    ldsm_x4t(avh[mb][0], avh[mb][1], avh[mb][2], avh[mb][3], adr);
                    ldsm_x4t(avl[mb][0], avl[mb][1], avl[mb][2], avl[mb][3], adr + 16384);
                }
            }
            u32 bh[8][2], bl[8][2];
            {
                int row = kk + ((lane >> 3) & 1) * 8 + (lane & 7);
                int cb = (m0w >> 3) + ((lane >> 4) & 1);
                #pragma unroll
                for (int nbp = 0; nbp < 4; nbp++) {
                    int chunk = (cb + nbp * 2) ^ (row & 7);
                    u32 adr = sbase + KV_SKP + row * 256 + (chunk << 4);
                    u32 r0, r1, r2, r3;
                    ldsm_x4t(r0, r1, r2, r3, adr);
                    bh[2 * nbp][0] = r0; bh[2 * nbp][1] = r1;
                    bh[2 * nbp + 1][0] = r2; bh[2 * nbp + 1][1] = r3;
                    ldsm_x4t(r0, r1, r2, r3, adr + 16384);
                    bl[2 * nbp][0] = r0; bl[2 * nbp][1] = r1;
                    bl[2 * nbp + 1][0] = r2; bl[2 * nbp + 1][1] = r3;
                }
            }
            #pragma unroll
            for (int mb = 0; mb < 2; mb++)
                #pragma unroll
                for (int nb = 0; nb < 8; nb++) {
                    mma_bf16(c[mb][nb], avh[mb], bh[nb]);
                    mma_bf16(c[mb][nb], avl[mb], bh[nb]);
                    mma_bf16(c[mb][nb], avh[mb], bl[nb]);
                }
        }
        __syncthreads();
    }

    float* outp = g_KVpart[split];
    #pragma unroll
    for (int mb = 0; mb < 2; mb++)
        #pragma unroll
        for (int nb = 0; nb < 8; nb++) {
            int dv = dv0 + mb * 16 + gid;
            int m = m0blk + m0w + nb * 8 + 2 * tig;
            *(float2*)&outp[(size_t)(b * DVV + dv) * MM + m] =
                make_float2(c[mb][nb][0], c[mb][nb][1]);
            *(float2*)&outp[(size_t)(b * DVV + dv + 8) * MM + m] =
                make_float2(c[mb][nb][2], c[mb][nb][3]);
        }

    // ksum: sKs [16 ng][128 m] f32 (overlays sV)
    float* sKs = (float*)dyn;
    __syncthreads();
    #pragma unroll
    for (int i = 0; i < 8; i++) sKs[ng * 128 + mg2 * 8 + i] = ksloc[i];
    __syncthreads();
    if (tid < 128) {
        float s = 0.f;
        #pragma unroll
        for (int r = 0; r < 16; r++) s += sKs[r * 128 + tid];
        g_KsumPart[split][b * MM + m0blk + tid] = s;
    }
}

__global__ void reduce_kernel() {
    int i = blockIdx.x * 256 + threadIdx.x;
    if (i < BB * DVV * MM) {
        float s = 0.f;
        #pragma unroll
        for (int p = 0; p < NSPLIT; p++) s += g_KVpart[p][i];
        __nv_bfloat16 h = __float2bfloat16(s);
        g_KVT_hi[i] = h;
        g_KVT_lo[i] = __float2bfloat16(s - __bfloat162float(h));
    }
    int j = i - BB * DVV * MM;
    if (j >= 0 && j < BB * MM) {
        float s = 0.f;
        #pragma unroll
        for (int p = 0; p < NSPLIT; p++) s += g_KsumPart[p][j];
        g_Ksum[j] = s;
    }
}

// ---------------------------------------------------------------------------
// out_mma: Out[tok][dv] = (sum_m Qp[tok][m]*KVT[dv][m]) * rinv[tok]
// CTA 128 tok x 128 dv, K=256 in 4 chunks of 64. Warp 32 tok x 64 dv.
// ---------------------------------------------------------------------------
#define O_SA 0
#define O_SA_LO 16384
#define O_SB 32768
#define O_SB_LO 49152
#define O_SMEM 65536

__global__ void __launch_bounds__(256)
out_mma(float* __restrict__ out) {
    extern __shared__ __align__(16) char dyn[];
    const int tid = threadIdx.x;
    const int lane = tid & 31;
    const int w = tid >> 5;
    const int b = blockIdx.y;
    const int n0 = blockIdx.x * 128;
    const u32 sbase = smem_u32(dyn);

    const int tok0 = (w & 3) * 32;
    const int dv0 = (w >> 2) * 64;
    const int gid = lane >> 2, tig = lane & 3;

    float c[2][8][4];
    #pragma unroll
    for (int mb = 0; mb < 2; mb++)
        #pragma unroll
        for (int nb = 0; nb < 8; nb++)
            #pragma unroll
            for (int q = 0; q < 4; q++) c[mb][nb][q] = 0.f;

    const int rowA0 = tok0 + ((lane >> 3) & 1) * 8 + (lane & 7);
    const int kselA = (lane >> 4) & 1;
    const int rowB0 = dv0 + ((lane >> 4) & 1) * 8 + (lane & 7);
    const int kselB = (lane >> 3) & 1;

    for (int kc = 0; kc < 4; kc++) {
        const int mbase = kc * 64;
        {
            int row = tid >> 1, hf = tid & 1;
            const uint4* ah = (const uint4*)(g_Qp_hi + ((size_t)(b * NN + n0 + row)) * MM + mbase + hf * 32);
            const uint4* al = (const uint4*)(g_Qp_lo + ((size_t)(b * NN + n0 + row)) * MM + mbase + hf * 32);
            const uint4* kh = (const uint4*)(g_KVT_hi + (size_t)(b * DVV + row) * MM + mbase + hf * 32);
            const uint4* kl = (const uint4*)(g_KVT_lo + (size_t)(b * DVV + row) * MM + mbase + hf * 32);
            #pragma unroll
            for (int q = 0; q < 4; q++) {
                int chunk = (hf * 4 + q) ^ (row & 7);
                *(uint4*)(dyn + O_SA + row * 128 + (chunk << 4)) = ah[q];
                *(uint4*)(dyn + O_SA_LO + row * 128 + (chunk << 4)) = al[q];
                *(uint4*)(dyn + O_SB + row * 128 + (chunk << 4)) = kh[q];
                *(uint4*)(dyn + O_SB_LO + row * 128 + (chunk << 4)) = kl[q];
            }
        }
        __syncthreads();
        #pragma unroll
        for (int ks = 0; ks < 4; ks++) {
            int kcc = ks * 2;
            u32 ah[2][4], al[2][4];
            #pragma unroll
            for (int mb = 0; mb < 2; mb++) {
                int row = rowA0 + mb * 16;
                u32 adr = sbase + O_SA + row * 128 + (((kcc + kselA) ^ (row & 7)) << 4);
                ldsm_x4(ah[mb][0], ah[mb][1], ah[mb][2], ah[mb][3], adr);
                ldsm_x4(al[mb][0], al[mb][1], al[mb][2], al[mb][3], adr + 16384);
            }
            u32 bh[8][2], bl[8][2];
            #pragma unroll
            for (int nbp = 0; nbp < 4; nbp++) {
                int row = rowB0 + nbp * 16;
                u32 adr = sbase + O_SB + row * 128 + (((kcc + kselB) ^ (row & 7)) << 4);
                u32 r0, r1, r2, r3;
                ldsm_x4(r0, r1, r2, r3, adr);
                bh[2 * nbp][0] = r0; bh[2 * nbp][1] = r1;
                bh[2 * nbp + 1][0] = r2; bh[2 * nbp + 1][1] = r3;
                ldsm_x4(r0, r1, r2, r3, adr + 16384);
                bl[2 * nbp][0] = r0; bl[2 * nbp][1] = r1;
                bl[2 * nbp + 1][0] = r2; bl[2 * nbp + 1][1] = r3;
            }
            #pragma unroll
            for (int mb = 0; mb < 2; mb++)
                #pragma unroll
                for (int nb = 0; nb < 8; nb++) {
                    mma_bf16(c[mb][nb], ah[mb], bh[nb]);
                    mma_bf16(c[mb][nb], al[mb], bh[nb]);
                    mma_bf16(c[mb][nb], ah[mb], bl[nb]);
                }
        }
        __syncthreads();
    }

    #pragma unroll
    for (int mb = 0; mb < 2; mb++) {
        int t0 = tok0 + mb * 16 + gid;
        float r0 = g_rinv[b * NN + n0 + t0];
        float r1 = g_rinv[b * NN + n0 + t0 + 8];
        float* d0 = out + ((size_t)(b * NN + n0 + t0)) * DVV;
        float* d1 = d0 + (size_t)8 * DVV;
        #pragma unroll
        for (int nb = 0; nb < 8; nb++) {
            int dv = dv0 + nb * 8 + 2 * tig;
            *(float2*)(d0 + dv) = make_float2(c[mb][nb][0] * r0, c[mb][nb][1] * r0);
            *(float2*)(d1 + dv) = make_float2(c[mb][nb][2] * r1, c[mb][nb][3] * r1);
        }
    }
}

// ---------------------------------------------------------------------------
extern "C" void kernel_launch(void* const* d_in, const int* in_sizes, int n_in,
                              void* d_out, int out_size) {
    const float* Q     = (const float*)d_in[0];
    const float* K     = (const float*)d_in[1];
    const float* V     = (const float*)d_in[2];
    const float* amask = (const float*)d_in[3];
    const float* omega = (const float*)d_in[4];
    float* out = (float*)d_out;

    cudaFuncSetAttribute(kproj_mma, cudaFuncAttributeMaxDynamicSharedMemorySize, P_SMEM);
    cudaFuncSetAttribute(qproj_mma, cudaFuncAttributeMaxDynamicSharedMemorySize, P_SMEM);
    cudaFuncSetAttribute(kv_mma,    cudaFuncAttributeMaxDynamicSharedMemorySize, KV_SMEM);
    cudaFuncSetAttribute(out_mma,   cudaFuncAttributeMaxDynamicSharedMemorySize, O_SMEM);

    init_kernel<<<1, 32>>>();
    prep_omega<<<64, 256>>>(omega);
    kproj_mma<<<dim3(NN / 64, BB), 256, P_SMEM>>>(K);
    kv_mma<<<dim3(NSPLIT, MM / 128, BB), 256, KV_SMEM>>>(V, amask);
    reduce_kernel<<<(BB * DVV * MM + BB * MM + 255) / 256, 256>>>();
    qproj_mma<<<dim3(NN / 64, BB), 256, P_SMEM>>>(Q, amask);
    out_mma<<<dim3(NN / 128, BB), 256, O_SMEM>>>(out);
}

// round 8
// speedup vs baseline: 1.5709x; 1.1786x over previous
#include <cuda_runtime.h>
#include <cuda_bf16.h>
#include <math.h>

#define BB 8
#define NN 8192
#define DD 128
#define DVV 128
#define MM 256
#define NSPLIT 16

#define SCALE_U 0.29730177875068026f   // 128^-0.25
#define H_SCALE 0.04419417382415922f   // 1/(2*sqrt(128))
#define INV_SQRT_M 0.0625f             // 1/sqrt(256)

typedef unsigned long long ull;
typedef unsigned int u32;

// ---------------------------------------------------------------------------
// Device scratch
// ---------------------------------------------------------------------------
__device__ float g_U[(size_t)BB * NN * MM];      // raw scaled U (K pass, then Q pass)
__device__ float g_h[BB * NN];
__device__ float g_bmax[BB];
__device__ float g_KVpart[NSPLIT][BB * DVV * MM];   // KV^T partials [b][dv][m]
__device__ float g_KsumPart[NSPLIT][BB * MM];
__device__ float g_Ksum[BB * MM];
__device__ float g_rinv[BB * NN];
// omega pre-packed as mma B-fragments: [kstep(8)][nb(32)][reg(2)][lane(32)] u32
__device__ u32 g_wfrag_hi[8 * 32 * 2 * 32];
__device__ u32 g_wfrag_lo[8 * 32 * 2 * 32];
__device__ __nv_bfloat16 g_Qp_hi[(size_t)BB * NN * MM];   // [b][n][m]
__device__ __nv_bfloat16 g_Qp_lo[(size_t)BB * NN * MM];
__device__ __nv_bfloat16 g_KVT_hi[BB * DVV * MM];         // [b][dv][m]
__device__ __nv_bfloat16 g_KVT_lo[BB * DVV * MM];

// ---------------------------------------------------------------------------
// PTX helpers (sm_80-level)
// ---------------------------------------------------------------------------
__device__ __forceinline__ u32 smem_u32(const void* p) {
    u32 a;
    asm("{ .reg .u64 t; cvta.to.shared.u64 t, %1; cvt.u32.u64 %0, t; }" : "=r"(a) : "l"(p));
    return a;
}
__device__ __forceinline__ void ldsm_x4(u32& r0, u32& r1, u32& r2, u32& r3, u32 addr) {
    asm volatile("ldmatrix.sync.aligned.m8n8.x4.shared.b16 {%0,%1,%2,%3}, [%4];"
                 : "=r"(r0), "=r"(r1), "=r"(r2), "=r"(r3) : "r"(addr));
}
__device__ __forceinline__ void ldsm_x4t(u32& r0, u32& r1, u32& r2, u32& r3, u32 addr) {
    asm volatile("ldmatrix.sync.aligned.m8n8.x4.trans.shared.b16 {%0,%1,%2,%3}, [%4];"
                 : "=r"(r0), "=r"(r1), "=r"(r2), "=r"(r3) : "r"(addr));
}
__device__ __forceinline__ void mma_bf16(float* c, const u32* a, const u32* b) {
    asm volatile("mma.sync.aligned.m16n8k16.row.col.f32.bf16.bf16.f32 "
                 "{%0,%1,%2,%3}, {%4,%5,%6,%7}, {%8,%9}, {%0,%1,%2,%3};"
                 : "+f"(c[0]), "+f"(c[1]), "+f"(c[2]), "+f"(c[3])
                 : "r"(a[0]), "r"(a[1]), "r"(a[2]), "r"(a[3]), "r"(b[0]), "r"(b[1]));
}
__device__ __forceinline__ u32 bpack(float lo, float hi) {
    u32 r;
    asm("cvt.rn.bf16x2.f32 %0, %1, %2;" : "=r"(r) : "f"(hi), "f"(lo));
    return r;
}
__device__ __forceinline__ void cvt8(const float* x, uint4& h4, uint4& l4) {
    u32 h[4], l[4];
    #pragma unroll
    for (int i = 0; i < 4; i++) {
        u32 p = bpack(x[2 * i], x[2 * i + 1]);
        h[i] = p;
        float r0 = x[2 * i]     - __uint_as_float(p << 16);
        float r1 = x[2 * i + 1] - __uint_as_float(p & 0xFFFF0000u);
        l[i] = bpack(r0, r1);
    }
    h4 = make_uint4(h[0], h[1], h[2], h[3]);
    l4 = make_uint4(l[0], l[1], l[2], l[3]);
}

__device__ __forceinline__ float fexp(float x) {
    x = fmaxf(x, -87.0f);
    float t = x * 1.4426950408889634f;
    float r = rintf(t);
    float f = t - r;
    float z = f * 0.6931471805599453f;
    float p = 1.0f + z * (1.0f + z * (0.5f + z * (0.16666667f +
              z * (0.041666667f + z * (0.0083333333f + z * 0.0013888889f)))));
    return __int_as_float(((int)r + 127) << 23) * p;
}
__device__ __forceinline__ float warpMax(float v) {
    #pragma unroll
    for (int o = 16; o; o >>= 1) v = fmaxf(v, __shfl_xor_sync(0xffffffffu, v, o));
    return v;
}
__device__ __forceinline__ void atomicMaxFloat(float* addr, float val) {
    int old = __float_as_int(*addr);
    while (__int_as_float(old) < val) {
        int prev = atomicCAS((int*)addr, old, __float_as_int(val));
        if (prev == old) break;
        old = prev;
    }
}

__global__ void init_kernel() {
    if (threadIdx.x < BB) g_bmax[threadIdx.x] = -INFINITY;
}

// ---------------------------------------------------------------------------
// prep_omega: write omega (scaled, transposed) directly as B-fragments.
// ---------------------------------------------------------------------------
__global__ void prep_omega(const float* __restrict__ omega) {
    int id = blockIdx.x * 256 + threadIdx.x;   // 16384 total
    int m = id >> 6;
    int dp = id & 63;
    int d = dp * 2;
    float w0 = omega[(size_t)d * MM + m] * SCALE_U;
    float w1 = omega[(size_t)(d + 1) * MM + m] * SCALE_U;
    u32 hp = bpack(w0, w1);
    float r0 = w0 - __uint_as_float(hp << 16);
    float r1 = w1 - __uint_as_float(hp & 0xFFFF0000u);
    u32 lp = bpack(r0, r1);
    int idx = (((d >> 4) * 32 + (m >> 3)) * 2 + ((d >> 3) & 1)) * 32
            + (m & 7) * 4 + ((d & 7) >> 1);
    g_wfrag_hi[idx] = hp;
    g_wfrag_lo[idx] = lp;
}

// ---------------------------------------------------------------------------
// Projections: CTA = 64 tok x 256 m, K=128. Warp tile 32 tok x 64 m.
// B (omega) streamed per-nb from gmem frags to keep regs <= 128 (2 CTAs/SM).
// smem: sA hi@0 (16K) lo@16K; epilogue sU f32 [64][264] overlays from 0.
// ---------------------------------------------------------------------------
#define P_SA 0
#define P_SA_LO 16384
#define P_SMEM 67584
#define SU_STRIDE 264

__device__ __forceinline__ void proj_mma_main(
    const float* __restrict__ Xb, char* dyn, u32 sb,
    float c[2][8][4], float* sHred)
{
    const int tid = threadIdx.x;
    const int lane = tid & 31;
    const int w = tid >> 5;

    {   // A: 64 tok x 128 d, f32 -> bf16 hi/lo, swizzled; h partials
        int row = tid >> 2, seg = (tid & 3) * 32;
        const float* src = Xb + (size_t)row * DD + seg;
        float hs = 0.f;
        #pragma unroll
        for (int q = 0; q < 4; q++) {
            float x[8];
            float4 v0 = *(const float4*)(src + q * 8);
            float4 v1 = *(const float4*)(src + q * 8 + 4);
            x[0] = v0.x; x[1] = v0.y; x[2] = v0.z; x[3] = v0.w;
            x[4] = v1.x; x[5] = v1.y; x[6] = v1.z; x[7] = v1.w;
            #pragma unroll
            for (int e = 0; e < 8; e++) hs = fmaf(x[e], x[e], hs);
            uint4 h4, l4;
            cvt8(x, h4, l4);
            int chunk = ((seg >> 3) + q) ^ (row & 7);
            *(uint4*)(dyn + P_SA + row * 256 + (chunk << 4)) = h4;
            *(uint4*)(dyn + P_SA_LO + row * 256 + (chunk << 4)) = l4;
        }
        sHred[tid] = hs;
    }
    __syncthreads();

    const int tok0 = (w & 1) * 32;
    const int m0w = (w >> 1) * 64;
    const int rowA0 = tok0 + ((lane >> 3) & 1) * 8 + (lane & 7);
    const int kselA = (lane >> 4) & 1;
    const int nbBase = (m0w >> 3);

    #pragma unroll
    for (int ks = 0; ks < 8; ks++) {
        int kc = ks * 2;
        u32 ah[2][4], al[2][4];
        #pragma unroll
        for (int mb = 0; mb < 2; mb++) {
            int row = rowA0 + mb * 16;
            u32 adr = sb + P_SA + row * 256 + (((kc + kselA) ^ (row & 7)) << 4);
            ldsm_x4(ah[mb][0], ah[mb][1], ah[mb][2], ah[mb][3], adr);
            ldsm_x4(al[mb][0], al[mb][1], al[mb][2], al[mb][3], adr + 16384);
        }
        #pragma unroll
        for (int nb = 0; nb < 8; nb++) {   // stream B fragments (low reg pressure)
            int base = ((ks * 32 + nbBase + nb) * 2) * 32 + lane;
            u32 bh[2], bl[2];
            bh[0] = g_wfrag_hi[base];
            bh[1] = g_wfrag_hi[base + 32];
            bl[0] = g_wfrag_lo[base];
            bl[1] = g_wfrag_lo[base + 32];
            #pragma unroll
            for (int mb = 0; mb < 2; mb++) {
                mma_bf16(c[mb][nb], ah[mb], bh);
                mma_bf16(c[mb][nb], al[mb], bh);
                mma_bf16(c[mb][nb], ah[mb], bl);
            }
        }
    }
    __syncthreads();   // A reads done before sU overlays
}

__device__ __forceinline__ float store_sU(float c[2][8][4], float* sU, int tid) {
    const int lane = tid & 31, w = tid >> 5;
    const int tok0 = (w & 1) * 32, m0w = (w >> 1) * 64;
    const int gid = lane >> 2, tig = lane & 3;
    float lmax = -INFINITY;
    #pragma unroll
    for (int mb = 0; mb < 2; mb++)
        #pragma unroll
        for (int nb = 0; nb < 8; nb++) {
            int r0 = tok0 + mb * 16 + gid;
            int m = m0w + nb * 8 + 2 * tig;
            float2 p0 = make_float2(c[mb][nb][0], c[mb][nb][1]);
            float2 p1 = make_float2(c[mb][nb][2], c[mb][nb][3]);
            *(float2*)&sU[r0 * SU_STRIDE + m] = p0;
            *(float2*)&sU[(r0 + 8) * SU_STRIDE + m] = p1;
            lmax = fmaxf(lmax, fmaxf(fmaxf(p0.x, p0.y), fmaxf(p1.x, p1.y)));
        }
    return lmax;
}

__global__ void __launch_bounds__(256, 2)
kproj_mma(const float* __restrict__ Kin) {
    extern __shared__ __align__(16) char dyn[];
    __shared__ float sHred[256];
    __shared__ float wred[8];

    const int tid = threadIdx.x;
    const int b = blockIdx.y;
    const int n0 = blockIdx.x * 64;
    const u32 sbase = smem_u32(dyn);

    float c[2][8][4];
    #pragma unroll
    for (int mb = 0; mb < 2; mb++)
        #pragma unroll
        for (int nb = 0; nb < 8; nb++)
            #pragma unroll
            for (int q = 0; q < 4; q++) c[mb][nb][q] = 0.f;

    proj_mma_main(Kin + ((size_t)b * NN + n0) * DD, dyn, sbase, c, sHred);

    float* sU = (float*)dyn;
    float lmax = store_sU(c, sU, tid);
    __syncthreads();

    {
        int row = tid >> 2, seg = (tid & 3) * 64;
        float* dst = g_U + ((size_t)(b * NN + n0 + row)) * MM + seg;
        const float* srcr = sU + row * SU_STRIDE + seg;
        #pragma unroll
        for (int q = 0; q < 16; q++)
            *(float4*)(dst + q * 4) = *(const float4*)(srcr + q * 4);
    }
    if (tid < 64) {
        float h = sHred[tid * 4] + sHred[tid * 4 + 1] + sHred[tid * 4 + 2] + sHred[tid * 4 + 3];
        g_h[b * NN + n0 + tid] = h * H_SCALE;
    }
    lmax = warpMax(lmax);
    if ((tid & 31) == 0) wred[tid >> 5] = lmax;
    __syncthreads();
    if (tid == 0) {
        float m = wred[0];
        #pragma unroll
        for (int q = 1; q < 8; q++) m = fmaxf(m, wred[q]);
        atomicMaxFloat(&g_bmax[b], m);
    }
}

__global__ void __launch_bounds__(256, 2)
qproj_mma(const float* __restrict__ Qin, const float* __restrict__ mask) {
    extern __shared__ __align__(16) char dyn[];
    __shared__ float sHred[256];
    __shared__ float sKsum[MM];

    const int tid = threadIdx.x;
    const int b = blockIdx.y;
    const int n0 = blockIdx.x * 64;
    const u32 sbase = smem_u32(dyn);

    if (tid < MM) sKsum[tid] = g_Ksum[b * MM + tid];

    float c[2][8][4];
    #pragma unroll
    for (int mb = 0; mb < 2; mb++)
        #pragma unroll
        for (int nb = 0; nb < 8; nb++)
            #pragma unroll
            for (int q = 0; q < 4; q++) c[mb][nb][q] = 0.f;

    proj_mma_main(Qin + ((size_t)b * NN + n0) * DD, dyn, sbase, c, sHred);

    float* sU = (float*)dyn;
    (void)store_sU(c, sU, tid);
    __syncthreads();

    const int tok = tid >> 2, t4 = tid & 3;
    const int seg = t4 * 64;
    const float* Urow = sU + tok * SU_STRIDE + seg;

    float mx = -INFINITY;
    #pragma unroll
    for (int i = 0; i < 64; i++) mx = fmaxf(mx, Urow[i]);
    mx = fmaxf(mx, __shfl_xor_sync(0xffffffffu, mx, 1));
    mx = fmaxf(mx, __shfl_xor_sync(0xffffffffu, mx, 2));

    float h = (sHred[tok * 4] + sHred[tok * 4 + 1] + sHred[tok * 4 + 2] + sHred[tok * 4 + 3]) * H_SCALE;
    float s = INV_SQRT_M * mask[b * NN + n0 + tok];
    const size_t gbase = ((size_t)(b * NN + n0 + tok)) * MM + seg;

    float np = 0.f;
    #pragma unroll
    for (int q = 0; q < 8; q++) {
        u32 h4[4], l4[4];
        #pragma unroll
        for (int e = 0; e < 4; e++) {
            int i = q * 8 + 2 * e;
            float q0 = (fexp(Urow[i] - h - mx) + 1e-4f) * s;
            float q1 = (fexp(Urow[i + 1] - h - mx) + 1e-4f) * s;
            np = fmaf(q0, sKsum[seg + i], np);
            np = fmaf(q1, sKsum[seg + i + 1], np);
            u32 p = bpack(q0, q1);
            h4[e] = p;
            float r0 = q0 - __uint_as_float(p << 16);
            float r1 = q1 - __uint_as_float(p & 0xFFFF0000u);
            l4[e] = bpack(r0, r1);
        }
        *(uint4*)&g_Qp_hi[gbase + q * 8] = make_uint4(h4[0], h4[1], h4[2], h4[3]);
        *(uint4*)&g_Qp_lo[gbase + q * 8] = make_uint4(l4[0], l4[1], l4[2], l4[3]);
    }
    np += __shfl_xor_sync(0xffffffffu, np, 1);
    np += __shfl_xor_sync(0xffffffffu, np, 2);
    if (t4 == 0) g_rinv[b * NN + n0 + tok] = 1.0f / (np + 1e-8f);
}

// ---------------------------------------------------------------------------
// kv_mma: KVT[dv][m] = sum_n V[n][dv]*Kp[n][m]. CTA 128 dv x 128 m,
// warp tile 32 dv x 64 m. n-split of 512. B streamed per-nbp for regs<=128.
// ---------------------------------------------------------------------------
#define KV_SV 0
#define KV_SV_LO 16384
#define KV_SKP 32768
#define KV_SKP_LO 49152
#define KV_SMEM 65536

__global__ void __launch_bounds__(256, 2)
kv_mma(const float* __restrict__ V, const float* __restrict__ mask) {
    extern __shared__ __align__(16) char dyn[];

    const int tid = threadIdx.x;
    const int lane = tid & 31;
    const int w = tid >> 5;
    const int b = blockIdx.z;
    const int m0blk = blockIdx.y * 128;
    const int split = blockIdx.x;
    const float mx = g_bmax[b];
    const u32 sbase = smem_u32(dyn);

    const int dv0 = (w & 3) * 32;
    const int m0w = (w >> 2) * 64;
    const int gid = lane >> 2, tig = lane & 3;

    float c[2][8][4];
    #pragma unroll
    for (int mb = 0; mb < 2; mb++)
        #pragma unroll
        for (int nb = 0; nb < 8; nb++)
            #pragma unroll
            for (int q = 0; q < 4; q++) c[mb][nb][q] = 0.f;
    float ksloc[8];
    #pragma unroll
    for (int i = 0; i < 8; i++) ksloc[i] = 0.f;

    const int mg2 = tid & 15;          // Kp conv: m-group (8 m)
    const int ng = tid >> 4;           // Kp conv: n-group (4 n)

    const int nbase = split * (NN / NSPLIT);
    for (int ch = 0; ch < (NN / NSPLIT) / 64; ch++) {
        const int n0c = nbase + ch * 64;
        {   // V: [64 n][128 dv] -> bf16 hi/lo swizzled
            int row = tid >> 2, seg = (tid & 3) * 32;
            const float* src = V + ((size_t)(b * NN + n0c + row)) * DVV + seg;
            #pragma unroll
            for (int q = 0; q < 4; q++) {
                float x[8];
                float4 v0 = *(const float4*)(src + q * 8);
                float4 v1 = *(const float4*)(src + q * 8 + 4);
                x[0] = v0.x; x[1] = v0.y; x[2] = v0.z; x[3] = v0.w;
                x[4] = v1.x; x[5] = v1.y; x[6] = v1.z; x[7] = v1.w;
                uint4 h4, l4;
                cvt8(x, h4, l4);
                int chunk = ((seg >> 3) + q) ^ (row & 7);
                *(uint4*)(dyn + KV_SV + row * 256 + (chunk << 4)) = h4;
                *(uint4*)(dyn + KV_SV_LO + row * 256 + (chunk << 4)) = l4;
            }
        }
        {   // Kp: exp(U - h - mx), [64 n][128 m] bf16 hi/lo swizzled
            #pragma unroll
            for (int r = 0; r < 4; r++) {
                int n = ng * 4 + r;
                const float* up = g_U + ((size_t)(b * NN + n0c + n)) * MM + m0blk + mg2 * 8;
                float off = g_h[b * NN + n0c + n] + mx;
                float s = INV_SQRT_M * mask[b * NN + n0c + n];
                float kp[8];
                float4 u0 = *(const float4*)(up);
                float4 u1 = *(const float4*)(up + 4);
                kp[0] = (fexp(u0.x - off) + 1e-4f) * s;
                kp[1] = (fexp(u0.y - off) + 1e-4f) * s;
                kp[2] = (fexp(u0.z - off) + 1e-4f) * s;
                kp[3] = (fexp(u0.w - off) + 1e-4f) * s;
                kp[4] = (fexp(u1.x - off) + 1e-4f) * s;
                kp[5] = (fexp(u1.y - off) + 1e-4f) * s;
                kp[6] = (fexp(u1.z - off) + 1e-4f) * s;
                kp[7] = (fexp(u1.w - off) + 1e-4f) * s;
                #pragma unroll
                for (int i = 0; i < 8; i++) ksloc[i] += kp[i];
                uint4 h4, l4;
                cvt8(kp, h4, l4);
                int chunk = mg2 ^ (n & 7);
                *(uint4*)(dyn + KV_SKP + n * 256 + (chunk << 4)) = h4;
                *(uint4*)(dyn + KV_SKP_LO + n * 256 + (chunk << 4)) = l4;
            }
        }
        __syncthreads();

        #pragma unroll
        for (int ks = 0; ks < 4; ks++) {
            const int kk = ks * 16;
            u32 avh[2][4], avl[2][4];
            {
                int row = kk + ((lane >> 4) & 1) * 8 + (lane & 7);
                int cb = (dv0 >> 3) + ((lane >> 3) & 1);
                #pragma unroll
                for (int mb = 0; mb < 2; mb++) {
                    int chunk = (cb + mb * 2) ^ (row & 7);
                    u32 adr = sbase + KV_SV + row * 256 + (chunk << 4);
                    ldsm_x4t(avh[mb][0], avh[mb][1], avh[mb][2], avh[mb][3], adr);
                    ldsm_x4t(avl[mb][0], avl[mb][1], avl[mb][2], avl[mb][3], adr + 16384);
                }
            }
            {
                int row = kk + ((lane >> 3) & 1) * 8 + (lane & 7);
                int cb = (m0w >> 3) + ((lane >> 4) & 1);
                #pragma unroll
                for (int nbp = 0; nbp < 4; nbp++) {   // stream B per pair
                    int chunk = (cb + nbp * 2) ^ (row & 7);
                    u32 adr = sbase + KV_SKP + row * 256 + (chunk << 4);
                    u32 bh0[2], bh1[2], bl0[2], bl1[2];
                    ldsm_x4t(bh0[0], bh0[1], bh1[0], bh1[1], adr);
                    ldsm_x4t(bl0[0], bl0[1], bl1[0], bl1[1], adr + 16384);
                    #pragma unroll
                    for (int mb = 0; mb < 2; mb++) {
                        mma_bf16(c[mb][2 * nbp], avh[mb], bh0);
                        mma_bf16(c[mb][2 * nbp], avl[mb], bh0);
                        mma_bf16(c[mb][2 * nbp], avh[mb], bl0);
                        mma_bf16(c[mb][2 * nbp + 1], avh[mb], bh1);
                        mma_bf16(c[mb][2 * nbp + 1], avl[mb], bh1);
                        mma_bf16(c[mb][2 * nbp + 1], avh[mb], bl1);
                    }
                }
            }
        }
        __syncthreads();
    }

    float* outp = g_KVpart[split];
    #pragma unroll
    for (int mb = 0; mb < 2; mb++)
        #pragma unroll
        for (int nb = 0; nb < 8; nb++) {
            int dv = dv0 + mb * 16 + gid;
            int m = m0blk + m0w + nb * 8 + 2 * tig;
            *(float2*)&outp[(size_t)(b * DVV + dv) * MM + m] =
                make_float2(c[mb][nb][0], c[mb][nb][1]);
            *(float2*)&outp[(size_t)(b * DVV + dv + 8) * MM + m] =
                make_float2(c[mb][nb][2], c[mb][nb][3]);
        }

    // ksum: sKs [16 ng][128 m] f32 (overlays sV)
    float* sKs = (float*)dyn;
    __syncthreads();
    #pragma unroll
    for (int i = 0; i < 8; i++) sKs[ng * 128 + mg2 * 8 + i] = ksloc[i];
    __syncthreads();
    if (tid < 128) {
        float s = 0.f;
        #pragma unroll
        for (int r = 0; r < 16; r++) s += sKs[r * 128 + tid];
        g_KsumPart[split][b * MM + m0blk + tid] = s;
    }
}

__global__ void reduce_kernel() {
    int i = blockIdx.x * 256 + threadIdx.x;
    if (i < BB * DVV * MM) {
        float s = 0.f;
        #pragma unroll
        for (int p = 0; p < NSPLIT; p++) s += g_KVpart[p][i];
        __nv_bfloat16 h = __float2bfloat16(s);
        g_KVT_hi[i] = h;
        g_KVT_lo[i] = __float2bfloat16(s - __bfloat162float(h));
    }
    int j = i - BB * DVV * MM;
    if (j >= 0 && j < BB * MM) {
        float s = 0.f;
        #pragma unroll
        for (int p = 0; p < NSPLIT; p++) s += g_KsumPart[p][j];
        g_Ksum[j] = s;
    }
}

// ---------------------------------------------------------------------------
// out_mma: Out[tok][dv] = (sum_m Qp[tok][m]*KVT[dv][m]) * rinv[tok]
// CTA 128 tok x 128 dv, K=256 in 4 chunks of 64. Warp 32 tok x 64 dv.
// B streamed per-nbp for regs<=128 (2 CTAs/SM).
// ---------------------------------------------------------------------------
#define O_SA 0
#define O_SA_LO 16384
#define O_SB 32768
#define O_SB_LO 49152
#define O_SMEM 65536

__global__ void __launch_bounds__(256, 2)
out_mma(float* __restrict__ out) {
    extern __shared__ __align__(16) char dyn[];
    const int tid = threadIdx.x;
    const int lane = tid & 31;
    const int w = tid >> 5;
    const int b = blockIdx.y;
    const int n0 = blockIdx.x * 128;
    const u32 sbase = smem_u32(dyn);

    const int tok0 = (w & 3) * 32;
    const int dv0 = (w >> 2) * 64;
    const int gid = lane >> 2, tig = lane & 3;

    float c[2][8][4];
    #pragma unroll
    for (int mb = 0; mb < 2; mb++)
        #pragma unroll
        for (int nb = 0; nb < 8; nb++)
            #pragma unroll
            for (int q = 0; q < 4; q++) c[mb][nb][q] = 0.f;

    const int rowA0 = tok0 + ((lane >> 3) & 1) * 8 + (lane & 7);
    const int kselA = (lane >> 4) & 1;
    const int rowB0 = dv0 + ((lane >> 4) & 1) * 8 + (lane & 7);
    const int kselB = (lane >> 3) & 1;

    for (int kc = 0; kc < 4; kc++) {
        const int mbase = kc * 64;
        {
            int row = tid >> 1, hf = tid & 1;
            const uint4* ah = (const uint4*)(g_Qp_hi + ((size_t)(b * NN + n0 + row)) * MM + mbase + hf * 32);
            const uint4* al = (const uint4*)(g_Qp_lo + ((size_t)(b * NN + n0 + row)) * MM + mbase + hf * 32);
            const uint4* kh = (const uint4*)(g_KVT_hi + (size_t)(b * DVV + row) * MM + mbase + hf * 32);
            const uint4* kl = (const uint4*)(g_KVT_lo + (size_t)(b * DVV + row) * MM + mbase + hf * 32);
            #pragma unroll
            for (int q = 0; q < 4; q++) {
                int chunk = (hf * 4 + q) ^ (row & 7);
                *(uint4*)(dyn + O_SA + row * 128 + (chunk << 4)) = ah[q];
                *(uint4*)(dyn + O_SA_LO + row * 128 + (chunk << 4)) = al[q];
                *(uint4*)(dyn + O_SB + row * 128 + (chunk << 4)) = kh[q];
                *(uint4*)(dyn + O_SB_LO + row * 128 + (chunk << 4)) = kl[q];
            }
        }
        __syncthreads();
        #pragma unroll
        for (int ks = 0; ks < 4; ks++) {
            int kcc = ks * 2;
            u32 ah[2][4], al[2][4];
            #pragma unroll
            for (int mb = 0; mb < 2; mb++) {
                int row = rowA0 + mb * 16;
                u32 adr = sbase + O_SA + row * 128 + (((kcc + kselA) ^ (row & 7)) << 4);
                ldsm_x4(ah[mb][0], ah[mb][1], ah[mb][2], ah[mb][3], adr);
                ldsm_x4(al[mb][0], al[mb][1], al[mb][2], al[mb][3], adr + 16384);
            }
            #pragma unroll
            for (int nbp = 0; nbp < 4; nbp++) {   // stream B per pair
                int row = rowB0 + nbp * 16;
                u32 adr = sbase + O_SB + row * 128 + (((kcc + kselB) ^ (row & 7)) << 4);
                u32 bh0[2], bh1[2], bl0[2], bl1[2];
                ldsm_x4(bh0[0], bh0[1], bh1[0], bh1[1], adr);
                ldsm_x4(bl0[0], bl0[1], bl1[0], bl1[1], adr + 16384);
                #pragma unroll
                for (int mb = 0; mb < 2; mb++) {
                    mma_bf16(c[mb][2 * nbp], ah[mb], bh0);
                    mma_bf16(c[mb][2 * nbp], al[mb], bh0);
                    mma_bf16(c[mb][2 * nbp], ah[mb], bl0);
                    mma_bf16(c[mb][2 * nbp + 1], ah[mb], bh1);
                    mma_bf16(c[mb][2 * nbp + 1], al[mb], bh1);
                    mma_bf16(c[mb][2 * nbp + 1], ah[mb], bl1);
                }
            }
        }
        __syncthreads();
    }

    #pragma unroll
    for (int mb = 0; mb < 2; mb++) {
        int t0 = tok0 + mb * 16 + gid;
        float r0 = g_rinv[b * NN + n0 + t0];
        float r1 = g_rinv[b * NN + n0 + t0 + 8];
        float* d0 = out + ((size_t)(b * NN + n0 + t0)) * DVV;
        float* d1 = d0 + (size_t)8 * DVV;
        #pragma unroll
        for (int nb = 0; nb < 8; nb++) {
            int dv = dv0 + nb * 8 + 2 * tig;
            *(float2*)(d0 + dv) = make_float2(c[mb][nb][0] * r0, c[mb][nb][1] * r0);
            *(float2*)(d1 + dv) = make_float2(c[mb][nb][2] * r1, c[mb][nb][3] * r1);
        }
    }
}

// ---------------------------------------------------------------------------
extern "C" void kernel_launch(void* const* d_in, const int* in_sizes, int n_in,
                              void* d_out, int out_size) {
    const float* Q     = (const float*)d_in[0];
    const float* K     = (const float*)d_in[1];
    const float* V     = (const float*)d_in[2];
    const float* amask = (const float*)d_in[3];
    const float* omega = (const float*)d_in[4];
    float* out = (float*)d_out;

    cudaFuncSetAttribute(kproj_mma, cudaFuncAttributeMaxDynamicSharedMemorySize, P_SMEM);
    cudaFuncSetAttribute(qproj_mma, cudaFuncAttributeMaxDynamicSharedMemorySize, P_SMEM);
    cudaFuncSetAttribute(kv_mma,    cudaFuncAttributeMaxDynamicSharedMemorySize, KV_SMEM);
    cudaFuncSetAttribute(out_mma,   cudaFuncAttributeMaxDynamicSharedMemorySize, O_SMEM);

    init_kernel<<<1, 32>>>();
    prep_omega<<<64, 256>>>(omega);
    kproj_mma<<<dim3(NN / 64, BB), 256, P_SMEM>>>(K);
    kv_mma<<<dim3(NSPLIT, MM / 128, BB), 256, KV_SMEM>>>(V, amask);
    reduce_kernel<<<(BB * DVV * MM + BB * MM + 255) / 256, 256>>>();
    qproj_mma<<<dim3(NN / 64, BB), 256, P_SMEM>>>(Q, amask);
    out_mma<<<dim3(NN / 128, BB), 256, O_SMEM>>>(out);
}